// round 3
// baseline (speedup 1.0000x reference)
#include <cuda_runtime.h>

#define Hd 256
#define Bb 32
#define Ss 48
#define Tt 48

// Scratch (device globals: no allocation allowed)
__device__ float g_XW0[Ss * Bb * Hd];          // src[s] @ W0
__device__ float g_YW0[Tt * Bb * Hd];          // trg[t] @ W0
__device__ float g_XW1[Ss * Tt * Bb * Hd];     // HX0[s,t] @ W1   (72 MB)
__device__ float g_YW1[Ss * Tt * Bb * Hd];     // HY0[s,t] @ W1   (72 MB)
__device__ float g_UI[2 * Hd * Hd * 2];        // interleaved (Ux[i][j], Uy[i][j]) per layer

// ---- packed fp32x2 helpers (ptxas will not auto-emit FFMA2 from C++) ----
__device__ __forceinline__ void fma2(unsigned long long& d, unsigned long long a, unsigned long long b) {
    asm("fma.rn.f32x2 %0, %1, %2, %0;" : "+l"(d) : "l"(a), "l"(b));
}
__device__ __forceinline__ unsigned long long dup2(float x) {
    unsigned long long r; asm("mov.b64 %0, {%1, %1};" : "=l"(r) : "f"(x)); return r;
}
__device__ __forceinline__ float2 unpk(unsigned long long v) {
    float2 f; asm("mov.b64 {%0, %1}, %2;" : "=f"(f.x), "=f"(f.y) : "l"(v)); return f;
}

// ---- build interleaved (Ux, Uy) pairs: g_UI[layer][i][j] = {Ux[i][j], Uy[i][j]} ----
__global__ void k_interleave(const float* __restrict__ U) {
    int idx = blockIdx.x * 256 + threadIdx.x;      // 0 .. 2*65536-1
    int d = idx >> 16;
    int r = idx & 0xFFFF;                          // i*256 + j
    const float* Ud = U + d * 2 * Hd * Hd;
    float ux = Ud[r];
    float uy = Ud[Hd * Hd + r];
    reinterpret_cast<float2*>(g_UI)[idx] = make_float2(ux, uy);
}

// ---- batched GEMM: C[g] = A[g] @ Wm   (A rows contiguous within a group) ----
// which: 0=g_XW0, 1=g_YW0, 2=g_XW1, 3=g_YW1
__global__ void __launch_bounds__(128) pre_kernel(const float* __restrict__ A, int gstride,
                                                  const float* __restrict__ Wm, int which) {
    __shared__ float smf[16 * 258 * 2];            // b-pairs interleaved, padded stride
    float* C = (which == 0) ? g_XW0 : (which == 1) ? g_YW0 : (which == 2) ? g_XW1 : g_YW1;

    int g = blockIdx.x, jb = blockIdx.y, tid = threadIdx.x;
    const float* Ag = A + (size_t)g * gstride;
    for (int idx = tid; idx < Bb * Hd; idx += 128) {
        int b = idx >> 8, i = idx & 255;
        smf[((b >> 1) * 258 + i) * 2 + (b & 1)] = Ag[idx];
    }
    __syncthreads();

    const unsigned long long* sm64 = reinterpret_cast<const unsigned long long*>(smf);
    int jq = tid & 15, bq = tid >> 4;
    int j0 = jb * 64 + jq * 4;
    const unsigned long long* mp0 = sm64 + (bq * 2) * 258;
    const unsigned long long* mp1 = sm64 + (bq * 2 + 1) * 258;

    unsigned long long a00 = 0, a01 = 0, a02 = 0, a03 = 0;
    unsigned long long a10 = 0, a11 = 0, a12 = 0, a13 = 0;
    const float4* Wr = reinterpret_cast<const float4*>(Wm + j0);

#pragma unroll 8
    for (int i = 0; i < 256; i++) {
        float4 w = Wr[i * 64];
        unsigned long long w0 = dup2(w.x), w1 = dup2(w.y), w2 = dup2(w.z), w3 = dup2(w.w);
        unsigned long long m0 = mp0[i], m1 = mp1[i];
        fma2(a00, m0, w0); fma2(a01, m0, w1); fma2(a02, m0, w2); fma2(a03, m0, w3);
        fma2(a10, m1, w0); fma2(a11, m1, w1); fma2(a12, m1, w2); fma2(a13, m1, w3);
    }

    float* Cg = C + (size_t)g * (Bb * Hd);
    float2 r00 = unpk(a00), r01 = unpk(a01), r02 = unpk(a02), r03 = unpk(a03);
    float2 r10 = unpk(a10), r11 = unpk(a11), r12 = unpk(a12), r13 = unpk(a13);
    int b0 = bq * 4;
    *reinterpret_cast<float4*>(&Cg[(b0 + 0) * Hd + j0]) = make_float4(r00.x, r01.x, r02.x, r03.x);
    *reinterpret_cast<float4*>(&Cg[(b0 + 1) * Hd + j0]) = make_float4(r00.y, r01.y, r02.y, r03.y);
    *reinterpret_cast<float4*>(&Cg[(b0 + 2) * Hd + j0]) = make_float4(r10.x, r11.x, r12.x, r13.x);
    *reinterpret_cast<float4*>(&Cg[(b0 + 3) * Hd + j0]) = make_float4(r10.y, r11.y, r12.y, r13.y);
}

// ---- wavefront diagonal kernel: one (cell, 64-col block) per CTA ----
__global__ void __launch_bounds__(128) diag_kernel(float* __restrict__ out,
                                                   const float* __restrict__ bias,
                                                   int layer, int k, int s_lo) {
    extern __shared__ float smf[];                 // (up,left) interleaved: [32][258][2]
    int tid = threadIdx.x;
    int s = s_lo + blockIdx.x;
    int t = k - s;

    int cell = (layer * Ss + s) * Tt + t;
    float* outc = out + (size_t)cell * 2 * Bb * Hd;
    const float* upp = (s > 0) ? out + (size_t)((layer * Ss + s - 1) * Tt + t) * 2 * Bb * Hd : nullptr;
    const float* lfp = (t > 0) ? out + (size_t)((layer * Ss + s) * Tt + t - 1) * 2 * Bb * Hd : nullptr;

    for (int idx = tid; idx < Bb * Hd; idx += 128) {
        int b = idx >> 8, i = idx & 255;
        float u = upp ? upp[idx] : 0.f;
        float l = lfp ? lfp[idx] : 0.f;
        *reinterpret_cast<float2*>(&smf[(b * 258 + i) * 2]) = make_float2(u, l);
    }
    __syncthreads();

    const unsigned long long* sm64 = reinterpret_cast<const unsigned long long*>(smf);
    int jq = tid & 15, bq = tid >> 4;
    int j0 = blockIdx.y * 64 + jq * 4;
    int b0 = bq * 4;

    const ulonglong2* UIp = reinterpret_cast<const ulonglong2*>(g_UI) + layer * 32768 + (j0 >> 1);
    const unsigned long long* m0p = sm64 + b0 * 258;
    const unsigned long long* m1p = m0p + 258;
    const unsigned long long* m2p = m1p + 258;
    const unsigned long long* m3p = m2p + 258;

    unsigned long long acc[4][4] = {};             // [bb][jj]: lo = up@Ux part, hi = left@Uy part

#pragma unroll 4
    for (int i = 0; i < 256; i++) {
        ulonglong2 wA = UIp[i * 128];              // packed (Ux,Uy) for j0, j0+1
        ulonglong2 wB = UIp[i * 128 + 1];          // j0+2, j0+3
        unsigned long long m0 = m0p[i], m1 = m1p[i], m2 = m2p[i], m3 = m3p[i];
        fma2(acc[0][0], m0, wA.x); fma2(acc[0][1], m0, wA.y); fma2(acc[0][2], m0, wB.x); fma2(acc[0][3], m0, wB.y);
        fma2(acc[1][0], m1, wA.x); fma2(acc[1][1], m1, wA.y); fma2(acc[1][2], m1, wB.x); fma2(acc[1][3], m1, wB.y);
        fma2(acc[2][0], m2, wA.x); fma2(acc[2][1], m2, wA.y); fma2(acc[2][2], m2, wB.x); fma2(acc[2][3], m2, wB.y);
        fma2(acc[3][0], m3, wA.x); fma2(acc[3][1], m3, wA.y); fma2(acc[3][2], m3, wB.x); fma2(acc[3][3], m3, wB.y);
    }

    const float* xw;
    const float* yw;
    if (layer == 0) {
        xw = g_XW0 + s * (Bb * Hd);
        yw = g_YW0 + t * (Bb * Hd);
    } else {
        int gc = s * Tt + t;
        xw = g_XW1 + (size_t)gc * (Bb * Hd);
        yw = g_YW1 + (size_t)gc * (Bb * Hd);
    }

    float4 bv = *reinterpret_cast<const float4*>(&bias[layer * Hd + j0]);
    float bja[4] = {bv.x, bv.y, bv.z, bv.w};

#pragma unroll
    for (int bb = 0; bb < 4; bb++) {
        int b = b0 + bb;
        float4 xv = *reinterpret_cast<const float4*>(&xw[b * Hd + j0]);
        float4 yv = *reinterpret_cast<const float4*>(&yw[b * Hd + j0]);
        float tmp[4];
#pragma unroll
        for (int jj = 0; jj < 4; jj++) {
            float2 p = unpk(acc[bb][jj]);
            tmp[jj] = p.x + p.y + bja[jj];         // up@Ux + left@Uy + b
        }
        float4 ox = make_float4(tanhf(xv.x + tmp[0]), tanhf(xv.y + tmp[1]),
                                tanhf(xv.z + tmp[2]), tanhf(xv.w + tmp[3]));
        float4 oy = make_float4(tanhf(yv.x + tmp[0]), tanhf(yv.y + tmp[1]),
                                tanhf(yv.z + tmp[2]), tanhf(yv.w + tmp[3]));
        *reinterpret_cast<float4*>(&outc[b * Hd + j0]) = ox;              // h_x (channel 0)
        *reinterpret_cast<float4*>(&outc[Bb * Hd + b * Hd + j0]) = oy;    // h_y (channel 1)
    }
}

extern "C" void kernel_launch(void* const* d_in, const int* in_sizes, int n_in,
                              void* d_out, int out_size) {
    const float* src  = (const float*)d_in[0];   // (48, 32, 256)
    const float* trg  = (const float*)d_in[1];   // (48, 32, 256)
    const float* W    = (const float*)d_in[2];   // (2, 256, 256)
    const float* U    = (const float*)d_in[3];   // (2, 512, 256)
    const float* bias = (const float*)d_in[4];   // (2, 1, 256)
    float* out = (float*)d_out;                  // (2, 48, 48, 2, 32, 256)

    cudaFuncSetAttribute(diag_kernel, cudaFuncAttributeMaxDynamicSharedMemorySize, 66048);

    // Build interleaved U operand
    k_interleave<<<512, 256>>>(U);

    // Layer-0 input GEMMs (broadcast structure: only 48+48 groups)
    pre_kernel<<<dim3(48, 4), 128>>>(src, Bb * Hd, W, 0);
    pre_kernel<<<dim3(48, 4), 128>>>(trg, Bb * Hd, W, 1);

    // Layer-0 wavefront
    for (int k = 0; k < Ss + Tt - 1; k++) {
        int s_lo = (k > Tt - 1) ? (k - (Tt - 1)) : 0;
        int s_hi = (k < Ss - 1) ? k : (Ss - 1);
        int n = s_hi - s_lo + 1;
        diag_kernel<<<dim3(n, 4), 128, 66048>>>(out, bias, 0, k, s_lo);
    }

    // Layer-1 input GEMMs (full grid: 2304 groups each, fully parallel)
    pre_kernel<<<dim3(2304, 4), 128>>>(out,            2 * Bb * Hd, W + Hd * Hd, 2);  // HX0 @ W1
    pre_kernel<<<dim3(2304, 4), 128>>>(out + Bb * Hd,  2 * Bb * Hd, W + Hd * Hd, 3);  // HY0 @ W1

    // Layer-1 wavefront
    for (int k = 0; k < Ss + Tt - 1; k++) {
        int s_lo = (k > Tt - 1) ? (k - (Tt - 1)) : 0;
        int s_hi = (k < Ss - 1) ? k : (Ss - 1);
        int n = s_hi - s_lo + 1;
        diag_kernel<<<dim3(n, 4), 128, 66048>>>(out, bias, 1, k, s_lo);
    }
}

// round 4
// speedup vs baseline: 2.4029x; 2.4029x over previous
#include <cuda_runtime.h>

#define Hd 256
#define Bb 32
#define Ss 48
#define Tt 48
#define NGRP 37   // 148 CTAs / 4 j-blocks

// Scratch (device globals: no allocation allowed)
__device__ float g_XW0[Ss * Bb * Hd];          // src[s] @ W0
__device__ float g_YW0[Tt * Bb * Hd];          // trg[t] @ W0
__device__ float g_XW1[Ss * Tt * Bb * Hd];     // HX0[s,t] @ W1   (72 MB)
__device__ float g_YW1[Ss * Tt * Bb * Hd];     // HY0[s,t] @ W1   (72 MB)
__device__ float g_UI[2 * Hd * Hd * 2];        // interleaved (Ux[i][j], Uy[i][j]) per layer
__device__ int   g_flag[2 * Ss * Tt];          // per-cell completion counters (4 = done)

// ---- packed fp32x2 helpers (ptxas will not auto-emit FFMA2 from C++) ----
__device__ __forceinline__ void fma2(unsigned long long& d, unsigned long long a, unsigned long long b) {
    asm("fma.rn.f32x2 %0, %1, %2, %0;" : "+l"(d) : "l"(a), "l"(b));
}
__device__ __forceinline__ unsigned long long dup2(float x) {
    unsigned long long r; asm("mov.b64 %0, {%1, %1};" : "=l"(r) : "f"(x)); return r;
}
__device__ __forceinline__ float2 unpk(unsigned long long v) {
    float2 f; asm("mov.b64 {%0, %1}, %2;" : "=f"(f.x), "=f"(f.y) : "l"(v)); return f;
}
__device__ __forceinline__ int ld_acq(const int* p) {
    int v; asm volatile("ld.acquire.gpu.global.b32 %0, [%1];" : "=r"(v) : "l"(p) : "memory"); return v;
}

__global__ void zero_flags() {
    int i = blockIdx.x * 512 + threadIdx.x;
    if (i < 2 * Ss * Tt) g_flag[i] = 0;
}

// ---- build interleaved (Ux, Uy) pairs: g_UI[layer][i][j] = {Ux[i][j], Uy[i][j]} ----
__global__ void k_interleave(const float* __restrict__ U) {
    int idx = blockIdx.x * 256 + threadIdx.x;      // 0 .. 2*65536-1
    int d = idx >> 16;
    int r = idx & 0xFFFF;                          // i*256 + j
    const float* Ud = U + d * 2 * Hd * Hd;
    float ux = Ud[r];
    float uy = Ud[Hd * Hd + r];
    reinterpret_cast<float2*>(g_UI)[idx] = make_float2(ux, uy);
}

// ---- batched GEMM: C[g] = A[g] @ Wm   (A rows contiguous within a group) ----
__global__ void __launch_bounds__(128) pre_kernel(const float* __restrict__ A, int gstride,
                                                  const float* __restrict__ Wm, int which) {
    __shared__ float smf[16 * 258 * 2];            // b-pairs interleaved, padded stride
    float* C = (which == 0) ? g_XW0 : (which == 1) ? g_YW0 : (which == 2) ? g_XW1 : g_YW1;

    int g = blockIdx.x, jb = blockIdx.y, tid = threadIdx.x;
    const float* Ag = A + (size_t)g * gstride;
    for (int idx = tid; idx < Bb * Hd; idx += 128) {
        int b = idx >> 8, i = idx & 255;
        smf[((b >> 1) * 258 + i) * 2 + (b & 1)] = Ag[idx];
    }
    __syncthreads();

    const unsigned long long* sm64 = reinterpret_cast<const unsigned long long*>(smf);
    int jq = tid & 15, bq = tid >> 4;
    int j0 = jb * 64 + jq * 4;
    const unsigned long long* mp0 = sm64 + (bq * 2) * 258;
    const unsigned long long* mp1 = sm64 + (bq * 2 + 1) * 258;

    unsigned long long a00 = 0, a01 = 0, a02 = 0, a03 = 0;
    unsigned long long a10 = 0, a11 = 0, a12 = 0, a13 = 0;
    const float4* Wr = reinterpret_cast<const float4*>(Wm + j0);

#pragma unroll 8
    for (int i = 0; i < 256; i++) {
        float4 w = Wr[i * 64];
        unsigned long long w0 = dup2(w.x), w1 = dup2(w.y), w2 = dup2(w.z), w3 = dup2(w.w);
        unsigned long long m0 = mp0[i], m1 = mp1[i];
        fma2(a00, m0, w0); fma2(a01, m0, w1); fma2(a02, m0, w2); fma2(a03, m0, w3);
        fma2(a10, m1, w0); fma2(a11, m1, w1); fma2(a12, m1, w2); fma2(a13, m1, w3);
    }

    float* Cg = C + (size_t)g * (Bb * Hd);
    float2 r00 = unpk(a00), r01 = unpk(a01), r02 = unpk(a02), r03 = unpk(a03);
    float2 r10 = unpk(a10), r11 = unpk(a11), r12 = unpk(a12), r13 = unpk(a13);
    int b0 = bq * 4;
    *reinterpret_cast<float4*>(&Cg[(b0 + 0) * Hd + j0]) = make_float4(r00.x, r01.x, r02.x, r03.x);
    *reinterpret_cast<float4*>(&Cg[(b0 + 1) * Hd + j0]) = make_float4(r00.y, r01.y, r02.y, r03.y);
    *reinterpret_cast<float4*>(&Cg[(b0 + 2) * Hd + j0]) = make_float4(r10.x, r11.x, r12.x, r13.x);
    *reinterpret_cast<float4*>(&Cg[(b0 + 3) * Hd + j0]) = make_float4(r10.y, r11.y, r12.y, r13.y);
}

// ---- persistent wavefront kernel: one layer per launch ----
// Grid = 148 CTAs, 128 threads. CTA (grp, jb): jb = fixed 64-col block, grp walks cells.
// Weights staged ONCE into smem; cells synchronized via per-cell flags.
__global__ void __launch_bounds__(128) wave_kernel(float* __restrict__ out,
                                                   const float* __restrict__ bias,
                                                   int layer) {
    extern __shared__ float sm[];
    // [0, 131072): weight chunks ws[256][32] of 16B (de-interleaved even/odd slots)
    // [131072, 197120): parent tile smf[32][258][2] floats
    ulonglong2* ws = reinterpret_cast<ulonglong2*>(sm);
    float* smf = sm + 32768;

    int tid = threadIdx.x;
    int jb = blockIdx.x & 3, grp = blockIdx.x >> 2;
    int j0base = jb * 64;

    // Stage this CTA's 128KB weight tile: chunk q (cols j0base+2q, +2q+1), slot = (q&1)*16 + q/2
    {
        const ulonglong2* UI2 = reinterpret_cast<const ulonglong2*>(g_UI) + layer * 32768 + (j0base >> 1);
        for (int idx = tid; idx < 8192; idx += 128) {
            int i = idx >> 5, q = idx & 31;
            int slot = ((q & 1) << 4) | (q >> 1);
            ws[i * 32 + slot] = UI2[i * 128 + q];
        }
    }
    __syncthreads();

    int jq = tid & 15, bq = tid >> 4;
    int j0 = j0base + jq * 4;
    int b0 = bq * 4;
    float4 bv = *reinterpret_cast<const float4*>(&bias[layer * Hd + j0]);

    const unsigned long long* sm64 = reinterpret_cast<const unsigned long long*>(smf);
    const unsigned long long* m0p = sm64 + b0 * 258;
    const unsigned long long* m1p = m0p + 258;
    const unsigned long long* m2p = m1p + 258;
    const unsigned long long* m3p = m2p + 258;

    int flg_base = layer * (Ss * Tt);

    for (int k = 0; k < Ss + Tt - 1; k++) {
        int s_lo = (k > Tt - 1) ? (k - (Tt - 1)) : 0;
        int s_hi = (k < Ss - 1) ? k : (Ss - 1);
        int w = s_hi - s_lo + 1;

        for (int c = grp; c < w; c += NGRP) {
            int s = s_lo + c;
            int t = k - s;
            int cell = s * Tt + t;

            // Wait for both parents (all 4 j-blocks each)
            if (tid == 0) {
                if (s > 0) while (ld_acq(&g_flag[flg_base + cell - Tt]) < 4) __nanosleep(32);
                if (t > 0) while (ld_acq(&g_flag[flg_base + cell - 1]) < 4) __nanosleep(32);
            }
            __syncthreads();

            // Stage parent h_x tiles interleaved (up, left)
            const float* up = (s > 0) ? out + (size_t)((layer * Ss + s - 1) * Tt + t) * 2 * (Bb * Hd) : nullptr;
            const float* lf = (t > 0) ? out + (size_t)((layer * Ss + s) * Tt + t - 1) * 2 * (Bb * Hd) : nullptr;
            for (int idx = tid; idx < 2048; idx += 128) {
                int b = idx >> 6, i4 = (idx & 63) << 2;
                float4 u = up ? *reinterpret_cast<const float4*>(&up[b * Hd + i4]) : make_float4(0.f, 0.f, 0.f, 0.f);
                float4 l = lf ? *reinterpret_cast<const float4*>(&lf[b * Hd + i4]) : make_float4(0.f, 0.f, 0.f, 0.f);
                float4* dst = reinterpret_cast<float4*>(&smf[(b * 258 + i4) * 2]);
                dst[0] = make_float4(u.x, l.x, u.y, l.y);
                dst[1] = make_float4(u.z, l.z, u.w, l.w);
            }
            __syncthreads();

            // Recurrent GEMM: acc.lo = up@Ux, acc.hi = left@Uy (all operands in smem)
            unsigned long long acc[4][4] = {};
#pragma unroll 4
            for (int i = 0; i < 256; i++) {
                ulonglong2 wA = ws[i * 32 + jq];        // pairs (j0, j0+1)
                ulonglong2 wB = ws[i * 32 + 16 + jq];   // pairs (j0+2, j0+3)
                unsigned long long m0 = m0p[i], m1 = m1p[i], m2 = m2p[i], m3 = m3p[i];
                fma2(acc[0][0], m0, wA.x); fma2(acc[0][1], m0, wA.y); fma2(acc[0][2], m0, wB.x); fma2(acc[0][3], m0, wB.y);
                fma2(acc[1][0], m1, wA.x); fma2(acc[1][1], m1, wA.y); fma2(acc[1][2], m1, wB.x); fma2(acc[1][3], m1, wB.y);
                fma2(acc[2][0], m2, wA.x); fma2(acc[2][1], m2, wA.y); fma2(acc[2][2], m2, wB.x); fma2(acc[2][3], m2, wB.y);
                fma2(acc[3][0], m3, wA.x); fma2(acc[3][1], m3, wA.y); fma2(acc[3][2], m3, wB.x); fma2(acc[3][3], m3, wB.y);
            }

            // Epilogue
            const float* xw;
            const float* yw;
            if (layer == 0) {
                xw = g_XW0 + s * (Bb * Hd);
                yw = g_YW0 + t * (Bb * Hd);
            } else {
                int gc = s * Tt + t;
                xw = g_XW1 + (size_t)gc * (Bb * Hd);
                yw = g_YW1 + (size_t)gc * (Bb * Hd);
            }
            float* outc = out + (size_t)((layer * Ss + s) * Tt + t) * 2 * (Bb * Hd);

            float bja[4] = {bv.x, bv.y, bv.z, bv.w};
#pragma unroll
            for (int bb = 0; bb < 4; bb++) {
                int b = b0 + bb;
                float4 xv = *reinterpret_cast<const float4*>(&xw[b * Hd + j0]);
                float4 yv = *reinterpret_cast<const float4*>(&yw[b * Hd + j0]);
                float tmp[4];
#pragma unroll
                for (int jj = 0; jj < 4; jj++) {
                    float2 p = unpk(acc[bb][jj]);
                    tmp[jj] = p.x + p.y + bja[jj];
                }
                float4 ox = make_float4(tanhf(xv.x + tmp[0]), tanhf(xv.y + tmp[1]),
                                        tanhf(xv.z + tmp[2]), tanhf(xv.w + tmp[3]));
                float4 oy = make_float4(tanhf(yv.x + tmp[0]), tanhf(yv.y + tmp[1]),
                                        tanhf(yv.z + tmp[2]), tanhf(yv.w + tmp[3]));
                *reinterpret_cast<float4*>(&outc[b * Hd + j0]) = ox;              // h_x
                *reinterpret_cast<float4*>(&outc[Bb * Hd + b * Hd + j0]) = oy;    // h_y
            }

            // Publish: make writes visible, then bump cell counter
            __threadfence();
            __syncthreads();   // also guards smf reuse on next cell
            if (tid == 0) atomicAdd(&g_flag[flg_base + cell], 1);
        }
    }
}

extern "C" void kernel_launch(void* const* d_in, const int* in_sizes, int n_in,
                              void* d_out, int out_size) {
    const float* src  = (const float*)d_in[0];   // (48, 32, 256)
    const float* trg  = (const float*)d_in[1];   // (48, 32, 256)
    const float* W    = (const float*)d_in[2];   // (2, 256, 256)
    const float* U    = (const float*)d_in[3];   // (2, 512, 256)
    const float* bias = (const float*)d_in[4];   // (2, 1, 256)
    float* out = (float*)d_out;                  // (2, 48, 48, 2, 32, 256)

    static const int WAVE_SMEM = 131072 + 16 * 258 * 2 * 2 * 4;  // 131072 + 66048 = 197120
    cudaFuncSetAttribute(wave_kernel, cudaFuncAttributeMaxDynamicSharedMemorySize, WAVE_SMEM);

    zero_flags<<<9, 512>>>();
    k_interleave<<<512, 256>>>(U);

    // Layer-0 input GEMMs (broadcast structure: only 48+48 groups)
    pre_kernel<<<dim3(48, 4), 128>>>(src, Bb * Hd, W, 0);
    pre_kernel<<<dim3(48, 4), 128>>>(trg, Bb * Hd, W, 1);

    // Layer-0 wavefront (persistent)
    wave_kernel<<<148, 128, WAVE_SMEM>>>(out, bias, 0);

    // Layer-1 input GEMMs (full grid: 2304 groups each)
    pre_kernel<<<dim3(2304, 4), 128>>>(out,           2 * Bb * Hd, W + Hd * Hd, 2);  // HX0 @ W1
    pre_kernel<<<dim3(2304, 4), 128>>>(out + Bb * Hd, 2 * Bb * Hd, W + Hd * Hd, 3);  // HY0 @ W1

    // Layer-1 wavefront (persistent)
    wave_kernel<<<148, 128, WAVE_SMEM>>>(out, bias, 1);
}

// round 8
// speedup vs baseline: 3.0099x; 1.2526x over previous
#include <cuda_runtime.h>

#define Hd 256
#define Bb 32
#define Ss 48
#define Tt 48
#define NGRP 37   // 148 CTAs / 4 j-blocks

// Scratch (device globals: no allocation allowed)
__device__ float g_XW0[Ss * Bb * Hd];          // src[s] @ W0
__device__ float g_YW0[Tt * Bb * Hd];          // trg[t] @ W0
__device__ float g_XW1[Ss * Tt * Bb * Hd];     // HX0[s,t] @ W1   (72 MB)
__device__ float g_YW1[Ss * Tt * Bb * Hd];     // HY0[s,t] @ W1   (72 MB)
__device__ float g_UI[2 * Hd * Hd * 2];        // interleaved (Ux[i][j], Uy[i][j]) per layer
__device__ int   g_flag[2 * Ss * Tt];          // per-cell completion counters (4 = done)

// ---- packed fp32x2 helpers (ptxas will not auto-emit FFMA2 from C++) ----
__device__ __forceinline__ void fma2(unsigned long long& d, unsigned long long a, unsigned long long b) {
    asm("fma.rn.f32x2 %0, %1, %2, %0;" : "+l"(d) : "l"(a), "l"(b));
}
__device__ __forceinline__ unsigned long long dup2(float x) {
    unsigned long long r; asm("mov.b64 %0, {%1, %1};" : "=l"(r) : "f"(x)); return r;
}
__device__ __forceinline__ float2 unpk(unsigned long long v) {
    float2 f; asm("mov.b64 {%0, %1}, %2;" : "=f"(f.x), "=f"(f.y) : "l"(v)); return f;
}
__device__ __forceinline__ int ld_acq(const int* p) {
    int v; asm volatile("ld.acquire.gpu.global.b32 %0, [%1];" : "=r"(v) : "l"(p) : "memory"); return v;
}
__device__ __forceinline__ void red_release(int* p) {
    asm volatile("red.release.gpu.global.add.u32 [%0], %1;" :: "l"(p), "r"(1) : "memory");
}
// fast tanh: ~5 instr, rel err ~2e-6 (budget 1e-3)
__device__ __forceinline__ float ftanh(float x) {
    x = fminf(fmaxf(x, -20.f), 20.f);
    float e = __expf(2.f * x);
    return __fdividef(e - 1.f, e + 1.f);
}

__global__ void zero_flags() {
    int i = blockIdx.x * 512 + threadIdx.x;
    if (i < 2 * Ss * Tt) g_flag[i] = 0;
}

// ---- build interleaved (Ux, Uy) pairs: g_UI[layer][i][j] = {Ux[i][j], Uy[i][j]} ----
__global__ void k_interleave(const float* __restrict__ U) {
    int idx = blockIdx.x * 256 + threadIdx.x;      // 0 .. 2*65536-1
    int d = idx >> 16;
    int r = idx & 0xFFFF;                          // i*256 + j
    const float* Ud = U + d * 2 * Hd * Hd;
    float ux = Ud[r];
    float uy = Ud[Hd * Hd + r];
    reinterpret_cast<float2*>(g_UI)[idx] = make_float2(ux, uy);
}

// ---- batched GEMM: C[g] = A[g] @ Wm. blockIdx.z selects x/y side ----
__global__ void __launch_bounds__(128) pre_kernel(const float* __restrict__ Ax,
                                                  const float* __restrict__ Ay,
                                                  int gstride,
                                                  const float* __restrict__ Wm, int mode) {
    __shared__ float smf[16 * 258 * 2];            // b-pairs interleaved, padded stride
    int z = blockIdx.z;
    const float* A = z ? Ay : Ax;
    float* C = (mode == 0) ? (z ? g_YW0 : g_XW0) : (z ? g_YW1 : g_XW1);

    int g = blockIdx.x, jb = blockIdx.y, tid = threadIdx.x;
    const float* Ag = A + (size_t)g * gstride;
    for (int idx = tid; idx < Bb * Hd; idx += 128) {
        int b = idx >> 8, i = idx & 255;
        smf[((b >> 1) * 258 + i) * 2 + (b & 1)] = Ag[idx];
    }
    __syncthreads();

    const unsigned long long* sm64 = reinterpret_cast<const unsigned long long*>(smf);
    int jq = tid & 15, bq = tid >> 4;
    int j0 = jb * 64 + jq * 4;
    const unsigned long long* mp0 = sm64 + (bq * 2) * 258;
    const unsigned long long* mp1 = sm64 + (bq * 2 + 1) * 258;

    unsigned long long a00 = 0, a01 = 0, a02 = 0, a03 = 0;
    unsigned long long a10 = 0, a11 = 0, a12 = 0, a13 = 0;
    const float4* Wr = reinterpret_cast<const float4*>(Wm + j0);

#pragma unroll 8
    for (int i = 0; i < 256; i++) {
        float4 w = Wr[i * 64];
        unsigned long long w0 = dup2(w.x), w1 = dup2(w.y), w2 = dup2(w.z), w3 = dup2(w.w);
        unsigned long long m0 = mp0[i], m1 = mp1[i];
        fma2(a00, m0, w0); fma2(a01, m0, w1); fma2(a02, m0, w2); fma2(a03, m0, w3);
        fma2(a10, m1, w0); fma2(a11, m1, w1); fma2(a12, m1, w2); fma2(a13, m1, w3);
    }

    float* Cg = C + (size_t)g * (Bb * Hd);
    float2 r00 = unpk(a00), r01 = unpk(a01), r02 = unpk(a02), r03 = unpk(a03);
    float2 r10 = unpk(a10), r11 = unpk(a11), r12 = unpk(a12), r13 = unpk(a13);
    int b0 = bq * 4;
    *reinterpret_cast<float4*>(&Cg[(b0 + 0) * Hd + j0]) = make_float4(r00.x, r01.x, r02.x, r03.x);
    *reinterpret_cast<float4*>(&Cg[(b0 + 1) * Hd + j0]) = make_float4(r00.y, r01.y, r02.y, r03.y);
    *reinterpret_cast<float4*>(&Cg[(b0 + 2) * Hd + j0]) = make_float4(r10.x, r11.x, r12.x, r13.x);
    *reinterpret_cast<float4*>(&Cg[(b0 + 3) * Hd + j0]) = make_float4(r10.y, r11.y, r12.y, r13.y);
}

// ---- persistent wavefront kernel: one layer per launch ----
// Grid = 148 CTAs, 256 threads (8 warps, 2/SMSP). CTA (grp, jb).
// Warp w: jhalf = w&1 (8 jq each), bgroup = w>>2? -> see mapping below.
__global__ void __launch_bounds__(256, 1) wave_kernel(float* __restrict__ out,
                                                      const float* __restrict__ bias,
                                                      int layer) {
    extern __shared__ float sm[];
    // [0, 131072): weight chunks ws[256][32] of 16B (de-interleaved even/odd slots)
    // [131072, 197120): parent tile smf[32][258][2] floats
    ulonglong2* ws = reinterpret_cast<ulonglong2*>(sm);
    float* smf = sm + 32768;

    int tid = threadIdx.x;
    int jb = blockIdx.x & 3, grp = blockIdx.x >> 2;
    int j0base = jb * 64;

    // Stage this CTA's 128KB weight tile once
    {
        const ulonglong2* UI2 = reinterpret_cast<const ulonglong2*>(g_UI) + layer * 32768 + (j0base >> 1);
        for (int idx = tid; idx < 8192; idx += 256) {
            int i = idx >> 5, q = idx & 31;
            int slot = ((q & 1) << 4) | (q >> 1);
            ws[i * 32 + slot] = UI2[i * 128 + q];
        }
    }
    __syncthreads();

    // Thread decomposition: warp = (jhalf, bgroup); lane = (bsub, jql)
    int w = tid >> 5, lane = tid & 31;
    int jhalf = w & 1, bgroup = w >> 1;            // bgroup 0..3 -> 8 b-rows
    int jql = lane & 7, bsub = lane >> 3;          // bsub 0..3 -> 2 b-rows
    int jq = jhalf * 8 + jql;
    int j0 = j0base + jq * 4;
    int b0 = bgroup * 8 + bsub * 2;                // rows b0, b0+1

    float4 bv = *reinterpret_cast<const float4*>(&bias[layer * Hd + j0]);

    const unsigned long long* sm64 = reinterpret_cast<const unsigned long long*>(smf);
    const unsigned long long* m0p = sm64 + b0 * 258;
    const unsigned long long* m1p = m0p + 258;

    int flg_base = layer * (Ss * Tt);

    for (int k = 0; k < Ss + Tt - 1; k++) {
        int s_lo = (k > Tt - 1) ? (k - (Tt - 1)) : 0;
        int s_hi = (k < Ss - 1) ? k : (Ss - 1);
        int wdt = s_hi - s_lo + 1;

        for (int c = grp; c < wdt; c += NGRP) {
            int s = s_lo + c;
            int t = k - s;
            int cell = s * Tt + t;

            // Prefetch epilogue operands (independent of parents)
            const float* xw;
            const float* yw;
            if (layer == 0) {
                xw = g_XW0 + s * (Bb * Hd);
                yw = g_YW0 + t * (Bb * Hd);
            } else {
                int gc = s * Tt + t;
                xw = g_XW1 + (size_t)gc * (Bb * Hd);
                yw = g_YW1 + (size_t)gc * (Bb * Hd);
            }
            float4 xv0 = *reinterpret_cast<const float4*>(&xw[(b0 + 0) * Hd + j0]);
            float4 xv1 = *reinterpret_cast<const float4*>(&xw[(b0 + 1) * Hd + j0]);
            float4 yv0 = *reinterpret_cast<const float4*>(&yw[(b0 + 0) * Hd + j0]);
            float4 yv1 = *reinterpret_cast<const float4*>(&yw[(b0 + 1) * Hd + j0]);

            // Wait for both parents (all threads poll; acquire)
            if (s > 0) { const int* f = &g_flag[flg_base + cell - Tt]; while (ld_acq(f) < 4) __nanosleep(40); }
            if (t > 0) { const int* f = &g_flag[flg_base + cell - 1];  while (ld_acq(f) < 4) __nanosleep(40); }

            // Stage parent h_x tiles interleaved (up, left)
            const float* up = (s > 0) ? out + (size_t)((layer * Ss + s - 1) * Tt + t) * 2 * (Bb * Hd) : nullptr;
            const float* lf = (t > 0) ? out + (size_t)((layer * Ss + s) * Tt + t - 1) * 2 * (Bb * Hd) : nullptr;
            for (int idx = tid; idx < 2048; idx += 256) {
                int b = idx >> 6, i4 = (idx & 63) << 2;
                float4 u = up ? *reinterpret_cast<const float4*>(&up[b * Hd + i4]) : make_float4(0.f, 0.f, 0.f, 0.f);
                float4 l = lf ? *reinterpret_cast<const float4*>(&lf[b * Hd + i4]) : make_float4(0.f, 0.f, 0.f, 0.f);
                float4* dst = reinterpret_cast<float4*>(&smf[(b * 258 + i4) * 2]);
                dst[0] = make_float4(u.x, l.x, u.y, l.y);
                dst[1] = make_float4(u.z, l.z, u.w, l.w);
            }
            __syncthreads();

            // Recurrent GEMM: acc.lo = up@Ux, acc.hi = left@Uy (all operands in smem)
            unsigned long long acc[2][4] = {};
#pragma unroll 4
            for (int i = 0; i < 256; i++) {
                ulonglong2 wA = ws[i * 32 + jq];        // pairs (j0, j0+1)
                ulonglong2 wB = ws[i * 32 + 16 + jq];   // pairs (j0+2, j0+3)
                unsigned long long m0 = m0p[i], m1 = m1p[i];
                fma2(acc[0][0], m0, wA.x); fma2(acc[0][1], m0, wA.y); fma2(acc[0][2], m0, wB.x); fma2(acc[0][3], m0, wB.y);
                fma2(acc[1][0], m1, wA.x); fma2(acc[1][1], m1, wA.y); fma2(acc[1][2], m1, wB.x); fma2(acc[1][3], m1, wB.y);
            }

            // Epilogue
            float* outc = out + (size_t)((layer * Ss + s) * Tt + t) * 2 * (Bb * Hd);
            float bja[4] = {bv.x, bv.y, bv.z, bv.w};
            {
                float tmp0[4], tmp1[4];
#pragma unroll
                for (int jj = 0; jj < 4; jj++) {
                    float2 p0 = unpk(acc[0][jj]);
                    float2 p1 = unpk(acc[1][jj]);
                    tmp0[jj] = p0.x + p0.y + bja[jj];
                    tmp1[jj] = p1.x + p1.y + bja[jj];
                }
                float4 ox0 = make_float4(ftanh(xv0.x + tmp0[0]), ftanh(xv0.y + tmp0[1]),
                                         ftanh(xv0.z + tmp0[2]), ftanh(xv0.w + tmp0[3]));
                float4 oy0 = make_float4(ftanh(yv0.x + tmp0[0]), ftanh(yv0.y + tmp0[1]),
                                         ftanh(yv0.z + tmp0[2]), ftanh(yv0.w + tmp0[3]));
                float4 ox1 = make_float4(ftanh(xv1.x + tmp1[0]), ftanh(xv1.y + tmp1[1]),
                                         ftanh(xv1.z + tmp1[2]), ftanh(xv1.w + tmp1[3]));
                float4 oy1 = make_float4(ftanh(yv1.x + tmp1[0]), ftanh(yv1.y + tmp1[1]),
                                         ftanh(yv1.z + tmp1[2]), ftanh(yv1.w + tmp1[3]));
                *reinterpret_cast<float4*>(&outc[(b0 + 0) * Hd + j0]) = ox0;              // h_x
                *reinterpret_cast<float4*>(&outc[(b0 + 1) * Hd + j0]) = ox1;
                *reinterpret_cast<float4*>(&outc[Bb * Hd + (b0 + 0) * Hd + j0]) = oy0;    // h_y
                *reinterpret_cast<float4*>(&outc[Bb * Hd + (b0 + 1) * Hd + j0]) = oy1;
            }

            // Publish: bar orders all threads' STGs before the release-add.
            // (Also guards smf reuse by next cell's staging.)
            __syncthreads();
            if (tid == 0) red_release(&g_flag[flg_base + cell]);
        }
    }
}

extern "C" void kernel_launch(void* const* d_in, const int* in_sizes, int n_in,
                              void* d_out, int out_size) {
    const float* src  = (const float*)d_in[0];   // (48, 32, 256)
    const float* trg  = (const float*)d_in[1];   // (48, 32, 256)
    const float* W    = (const float*)d_in[2];   // (2, 256, 256)
    const float* U    = (const float*)d_in[3];   // (2, 512, 256)
    const float* bias = (const float*)d_in[4];   // (2, 1, 256)
    float* out = (float*)d_out;                  // (2, 48, 48, 2, 32, 256)

    static const int WAVE_SMEM = 131072 + 16 * 258 * 2 * 2 * 4;  // 197120
    cudaFuncSetAttribute(wave_kernel, cudaFuncAttributeMaxDynamicSharedMemorySize, WAVE_SMEM);

    zero_flags<<<9, 512>>>();
    k_interleave<<<512, 256>>>(U);

    // Layer-0 input GEMMs (x and y merged via grid.z)
    pre_kernel<<<dim3(48, 4, 2), 128>>>(src, trg, Bb * Hd, W, 0);

    // Layer-0 wavefront (persistent)
    wave_kernel<<<148, 256, WAVE_SMEM>>>(out, bias, 0);

    // Layer-1 input GEMMs (x and y merged via grid.z)
    pre_kernel<<<dim3(2304, 4, 2), 128>>>(out, out + Bb * Hd, 2 * Bb * Hd, W + Hd * Hd, 1);

    // Layer-1 wavefront (persistent)
    wave_kernel<<<148, 256, WAVE_SMEM>>>(out, bias, 1);
}